// round 10
// baseline (speedup 1.0000x reference)
#include <cuda_runtime.h>
#include <cuda_fp16.h>

#define N_NODES 100000
#define N_EDGES 1600000
#define IN_CH 128
#define ED_CH 32
#define HEADS 4
#define CH 32
#define HC 128
#define NEG_SLOPE 0.2f
#define SCAN_BLK 1024
#define N_SCAN_BLKS ((N_NODES + SCAN_BLK - 1) / SCAN_BLK)   // 98

// ---------------- scratch (no runtime allocation allowed) ----------------
__device__ __half g_xh_h[N_NODES * HC];         // 25.6 MB fp16 xh, [N,H,C]
__device__ float g_asrc[N_NODES * HEADS];
__device__ float g_adst[N_NODES * HEADS];
__device__ float g_weff[ED_CH * HEADS];         // folded W_edge @ att_edge
__device__ uint2 g_Wp[16 * 16 * 32];            // W packed as tf32 B-fragments
__device__ uint4 g_rec[N_EDGES];                // {src, ev01(h2), ev23(h2), 0} by dst
__device__ int   g_count[N_NODES];
__device__ int   g_rowptr[N_NODES + 1];
__device__ int   g_cursor[N_NODES];
__device__ int   g_bsum[N_SCAN_BLKS];
__device__ int   g_boff[N_SCAN_BLKS];

__device__ __forceinline__ unsigned tf32r(float f) {
    unsigned r;
    asm("cvt.rna.tf32.f32 %0, %1;" : "=r"(r) : "f"(f));
    return r;
}

__device__ __forceinline__ void mma_tf32(float c[4], unsigned a0, unsigned a1,
                                         unsigned a2, unsigned a3,
                                         unsigned b0, unsigned b1) {
    asm volatile(
        "mma.sync.aligned.m16n8k8.row.col.f32.tf32.tf32.f32 "
        "{%0,%1,%2,%3},{%4,%5,%6,%7},{%8,%9},{%0,%1,%2,%3};"
        : "+f"(c[0]), "+f"(c[1]), "+f"(c[2]), "+f"(c[3])
        : "r"(a0), "r"(a1), "r"(a2), "r"(a3), "r"(b0), "r"(b1));
}

// ---------------- init: zero edge counts ------------------------------------
__global__ void k_init() {
    int i = blockIdx.x * blockDim.x + threadIdx.x;
    if (i < N_NODES) g_count[i] = 0;
}

// ---------------- degree count: 4 edges per thread via int4 -----------------
__global__ __launch_bounds__(256) void k_count(const int* __restrict__ ei) {
    int i = blockIdx.x * 256 + threadIdx.x;        // int4 index
    if (i * 4 < N_EDGES) {
        int4 d4 = *(const int4*)(ei + N_EDGES + i * 4);
        atomicAdd(&g_count[d4.x], 1);
        atomicAdd(&g_count[d4.y], 1);
        atomicAdd(&g_count[d4.z], 1);
        atomicAdd(&g_count[d4.w], 1);
    }
}

// ---------------- W pack (blocks 0..31) | w_eff (block 32) ------------------
__global__ __launch_bounds__(256) void k_wpw(const float* __restrict__ W,
                                             const float* __restrict__ W_edge,
                                             const float* __restrict__ att_edge) {
    int b = blockIdx.x;
    int tid = threadIdx.x;
    if (b < 32) {
        int t = b * 256 + tid;  // 0..8191
        int lane = t & 31;
        int n = (t >> 5) & 15;
        int kk = t >> 9;
        int krow = 8 * kk + (lane & 3);
        int col = 8 * n + (lane >> 2);
        uint2 bb;
        bb.x = tf32r(W[krow * HC + col]);
        bb.y = tf32r(W[(krow + 4) * HC + col]);
        g_Wp[t] = bb;
    } else if (tid < 128) {
        int d = tid >> 2, h = tid & 3;
        float s = 0.f;
        #pragma unroll
        for (int c = 0; c < CH; c++)
            s += W_edge[d * HC + h * CH + c] * att_edge[h * CH + c];
        g_weff[d * HEADS + h] = s;
    }
}

// ---------------- xh = x @ W via tf32 mma + fused a_src/a_dst ---------------
__global__ __launch_bounds__(256) void k_gemm(const float* __restrict__ x,
                                              const float* __restrict__ att_src,
                                              const float* __restrict__ att_dst) {
    int tid  = threadIdx.x;
    int warp = tid >> 5;
    int lane = tid & 31;
    int grp  = lane >> 2;      // 0..7 (row within fragment)
    int q    = lane & 3;       // quad id (col group)

    int r0  = blockIdx.x * 128 + warp * 16;
    int rlo = r0 + grp;
    int rhi = rlo + 8;
    int rloL = rlo < N_NODES ? rlo : N_NODES - 1;
    int rhiL = rhi < N_NODES ? rhi : N_NODES - 1;
    const float* xlo = x + (size_t)rloL * IN_CH;
    const float* xhi = x + (size_t)rhiL * IN_CH;

    float c[16][4];
    #pragma unroll
    for (int n = 0; n < 16; n++) { c[n][0] = c[n][1] = c[n][2] = c[n][3] = 0.f; }

    #pragma unroll
    for (int kk = 0; kk < 16; kk++) {
        int k0 = 8 * kk;
        unsigned a0 = tf32r(__ldg(xlo + k0 + q));
        unsigned a1 = tf32r(__ldg(xhi + k0 + q));
        unsigned a2 = tf32r(__ldg(xlo + k0 + q + 4));
        unsigned a3 = tf32r(__ldg(xhi + k0 + q + 4));
        const uint2* wp = g_Wp + (size_t)kk * 16 * 32 + lane;
        #pragma unroll
        for (int n = 0; n < 16; n++) {
            uint2 b = __ldg(wp + n * 32);
            mma_tf32(c[n], a0, a1, a2, a3, b.x, b.y);
        }
    }

    float sl[4] = {0.f, 0.f, 0.f, 0.f}, dl[4] = {0.f, 0.f, 0.f, 0.f};
    float sh[4] = {0.f, 0.f, 0.f, 0.f}, dh[4] = {0.f, 0.f, 0.f, 0.f};
    bool wlo = rlo < N_NODES, whi = rhi < N_NODES;
    #pragma unroll
    for (int n = 0; n < 16; n++) {
        int col = 8 * n + 2 * q;
        int h = n >> 2;
        float as0 = __ldg(att_src + col), as1 = __ldg(att_src + col + 1);
        float ad0 = __ldg(att_dst + col), ad1 = __ldg(att_dst + col + 1);
        if (wlo)
            *(__half2*)(g_xh_h + (size_t)rlo * HC + col) =
                __floats2half2_rn(c[n][0], c[n][1]);
        if (whi)
            *(__half2*)(g_xh_h + (size_t)rhi * HC + col) =
                __floats2half2_rn(c[n][2], c[n][3]);
        sl[h] += c[n][0] * as0 + c[n][1] * as1;
        dl[h] += c[n][0] * ad0 + c[n][1] * ad1;
        sh[h] += c[n][2] * as0 + c[n][3] * as1;
        dh[h] += c[n][2] * ad0 + c[n][3] * ad1;
    }
    #pragma unroll
    for (int h = 0; h < 4; h++) {
        #pragma unroll
        for (int o = 1; o < 4; o <<= 1) {
            sl[h] += __shfl_xor_sync(0xffffffffu, sl[h], o);
            dl[h] += __shfl_xor_sync(0xffffffffu, dl[h], o);
            sh[h] += __shfl_xor_sync(0xffffffffu, sh[h], o);
            dh[h] += __shfl_xor_sync(0xffffffffu, dh[h], o);
        }
    }
    if (q == 0) {
        #pragma unroll
        for (int h = 0; h < 4; h++) {
            if (wlo) { g_asrc[rlo * HEADS + h] = sl[h]; g_adst[rlo * HEADS + h] = dl[h]; }
            if (whi) { g_asrc[rhi * HEADS + h] = sh[h]; g_adst[rhi * HEADS + h] = dh[h]; }
        }
    }
}

// ---------------- scan step 1: per-1024-block exclusive scan ---------------
__global__ __launch_bounds__(256) void k_scan1() {
    int b = blockIdx.x;
    int base = b * SCAN_BLK;
    int tid = threadIdx.x;
    int lane = tid & 31, w = tid >> 5;
    int v[4], ts = 0;
    #pragma unroll
    for (int j = 0; j < 4; j++) {
        int idx = base + tid * 4 + j;
        v[j] = (idx < N_NODES) ? g_count[idx] : 0;
        ts += v[j];
    }
    int incl = ts;
    #pragma unroll
    for (int o = 1; o < 32; o <<= 1) {
        int t = __shfl_up_sync(0xffffffffu, incl, o);
        if (lane >= o) incl += t;
    }
    __shared__ int wsum[8];
    if (lane == 31) wsum[w] = incl;
    __syncthreads();
    if (w == 0 && lane < 8) {
        int t = wsum[lane];
        #pragma unroll
        for (int o = 1; o < 8; o <<= 1) {
            int u = __shfl_up_sync(0xffu, t, o);
            if (lane >= o) t += u;
        }
        wsum[lane] = t;
    }
    __syncthreads();
    int excl = incl - ts + (w > 0 ? wsum[w - 1] : 0);
    int run = excl;
    #pragma unroll
    for (int j = 0; j < 4; j++) {
        int idx = base + tid * 4 + j;
        if (idx < N_NODES) g_rowptr[idx] = run;
        run += v[j];
    }
    __syncthreads();
    if (tid == 255) g_bsum[b] = wsum[7];
}

// ---------------- scan step 2: warp-parallel scan of 98 block sums ---------
__global__ void k_scan2() {
    int lane = threadIdx.x;            // 32 threads
    int run = 0;
    for (int b0 = 0; b0 < N_SCAN_BLKS; b0 += 32) {
        int i = b0 + lane;
        int v = (i < N_SCAN_BLKS) ? g_bsum[i] : 0;
        int incl = v;
        #pragma unroll
        for (int o = 1; o < 32; o <<= 1) {
            int t = __shfl_up_sync(0xffffffffu, incl, o);
            if (lane >= o) incl += t;
        }
        if (i < N_SCAN_BLKS) g_boff[i] = run + incl - v;
        run += __shfl_sync(0xffffffffu, incl, 31);
    }
    if (lane == 0) g_rowptr[N_NODES] = N_EDGES;
}

// ---------------- scan step 3: add offsets, init cursors -------------------
__global__ void k_scan3() {
    int i = blockIdx.x * blockDim.x + threadIdx.x;
    if (i >= N_NODES) return;
    int r = g_rowptr[i] + g_boff[i >> 10];
    g_rowptr[i] = r;
    g_cursor[i] = r;
}

// ---------------- fused edge pass: logits->exp + CSR scatter ---------------
// long-latency ops (ei loads, cursor atomic, asrc/adst gathers) issued BEFORE
// the smem staging + dot so their latency hides under compute.
__global__ __launch_bounds__(256) void k_edge_scatter(const int* __restrict__ ei,
                                                      const float* __restrict__ ea) {
    __shared__ float sEA[256][33];
    __shared__ float4 sW[32];
    int tid = threadIdx.x;
    int e0  = blockIdx.x * 256;
    int e   = e0 + tid;

    // early long-latency issues
    int src = __ldg(ei + e);
    int dst = __ldg(ei + N_EDGES + e);
    int pos = atomicAdd(&g_cursor[dst], 1);
    float4 as = __ldg((const float4*)(g_asrc) + src);
    float4 ad = __ldg((const float4*)(g_adst) + dst);

    if (tid < 32) sW[tid] = *(const float4*)(g_weff + tid * 4);

    const float4* gsrc = (const float4*)(ea + (size_t)e0 * ED_CH);
    #pragma unroll
    for (int k = 0; k < 8; k++) {
        int idx = tid + k * 256;
        float4 v = gsrc[idx];
        int row = idx >> 3;
        int col = (idx & 7) * 4;
        sEA[row][col + 0] = v.x; sEA[row][col + 1] = v.y;
        sEA[row][col + 2] = v.z; sEA[row][col + 3] = v.w;
    }
    __syncthreads();

    float s0 = 0.f, s1 = 0.f, s2 = 0.f, s3 = 0.f;
    #pragma unroll
    for (int d = 0; d < 32; d++) {
        float v = sEA[tid][d];
        float4 w = sW[d];
        s0 += v * w.x; s1 += v * w.y; s2 += v * w.z; s3 += v * w.w;
    }
    float l0 = as.x + ad.x + s0;
    float l1 = as.y + ad.y + s1;
    float l2 = as.z + ad.z + s2;
    float l3 = as.w + ad.w + s3;
    l0 = l0 >= 0.f ? l0 : NEG_SLOPE * l0;
    l1 = l1 >= 0.f ? l1 : NEG_SLOPE * l1;
    l2 = l2 >= 0.f ? l2 : NEG_SLOPE * l2;
    l3 = l3 >= 0.f ? l3 : NEG_SLOPE * l3;
    __half2 p0 = __floats2half2_rn(__expf(l0), __expf(l1));
    __half2 p1 = __floats2half2_rn(__expf(l2), __expf(l3));
    uint4 rec;
    rec.x = (unsigned)src;
    rec.y = *(unsigned*)&p0;
    rec.z = *(unsigned*)&p1;
    rec.w = 0u;
    g_rec[pos] = rec;          // single STG.128
}

// ---------------- aggregate: lane-per-(head,4ch), 2 edges in flight --------
__global__ __launch_bounds__(256) void k_agg(float* __restrict__ out,
                                             const float* __restrict__ gat_bias,
                                             const float* __restrict__ bias) {
    int n = blockIdx.x * 8 + (threadIdx.x >> 5);
    if (n >= N_NODES) return;
    int lane = threadIdx.x & 31;
    int h  = lane >> 3;            // head owned by this lane
    int c0 = 4 * (lane & 7);       // channel base (0..28)
    int beg = g_rowptr[n];
    int end = g_rowptr[n + 1];
    float a0 = 0.f, a1 = 0.f, a2 = 0.f, a3 = 0.f, dsum = 0.f;

    int idx = beg;
    for (; idx + 2 <= end; idx += 2) {
        uint4 r0 = __ldg(g_rec + idx);
        uint4 r1 = __ldg(g_rec + idx + 1);
        // two independent row gathers in flight
        uint2 xw0 = __ldg((const uint2*)(g_xh_h + (size_t)(int)r0.x * HC) + lane);
        uint2 xw1 = __ldg((const uint2*)(g_xh_h + (size_t)(int)r1.x * HC) + lane);
        unsigned eb0 = (h & 2) ? r0.z : r0.y;
        unsigned eb1 = (h & 2) ? r1.z : r1.y;
        float2 ep0 = __half22float2(*(__half2*)&eb0);
        float2 ep1 = __half22float2(*(__half2*)&eb1);
        float ev0 = (h & 1) ? ep0.y : ep0.x;
        float ev1 = (h & 1) ? ep1.y : ep1.x;
        float2 f00 = __half22float2(*(__half2*)&xw0.x);
        float2 f01 = __half22float2(*(__half2*)&xw0.y);
        float2 f10 = __half22float2(*(__half2*)&xw1.x);
        float2 f11 = __half22float2(*(__half2*)&xw1.y);
        a0 += ev0 * f00.x + ev1 * f10.x;
        a1 += ev0 * f00.y + ev1 * f10.y;
        a2 += ev0 * f01.x + ev1 * f11.x;
        a3 += ev0 * f01.y + ev1 * f11.y;
        dsum += ev0 + ev1;
    }
    if (idx < end) {
        uint4 r = __ldg(g_rec + idx);
        unsigned eb = (h & 2) ? r.z : r.y;
        float2 ep = __half22float2(*(__half2*)&eb);
        float ev = (h & 1) ? ep.y : ep.x;
        uint2 xw = __ldg((const uint2*)(g_xh_h + (size_t)(int)r.x * HC) + lane);
        float2 f0 = __half22float2(*(__half2*)&xw.x);
        float2 f1 = __half22float2(*(__half2*)&xw.y);
        a0 += ev * f0.x; a1 += ev * f0.y;
        a2 += ev * f1.x; a3 += ev * f1.y;
        dsum += ev;
    }

    float inv = dsum > 0.f ? 1.f / dsum : 0.f;
    a0 *= inv; a1 *= inv; a2 *= inv; a3 *= inv;
    #pragma unroll
    for (int o = 8; o < 32; o <<= 1) {
        a0 += __shfl_xor_sync(0xffffffffu, a0, o);
        a1 += __shfl_xor_sync(0xffffffffu, a1, o);
        a2 += __shfl_xor_sync(0xffffffffu, a2, o);
        a3 += __shfl_xor_sync(0xffffffffu, a3, o);
    }
    if (lane < 8) {
        float rr[4] = {a0, a1, a2, a3};
        float4 v4;
        float* vp = (float*)&v4;
        #pragma unroll
        for (int j = 0; j < 4; j++) {
            int c = c0 + j;
            float gb = 0.25f * (__ldg(gat_bias + c)      + __ldg(gat_bias + 32 + c) +
                                __ldg(gat_bias + 64 + c) + __ldg(gat_bias + 96 + c));
            float v = 0.25f * rr[j] + gb + __ldg(bias + c);
            vp[j] = v > 0.f ? v : 0.f;
        }
        *(float4*)(out + (size_t)n * CH + c0) = v4;
    }
}

extern "C" void kernel_launch(void* const* d_in, const int* in_sizes, int n_in,
                              void* d_out, int out_size) {
    const float* x        = (const float*)d_in[0];
    const int*   ei       = (const int*)  d_in[1];
    const float* ea       = (const float*)d_in[2];
    const float* W        = (const float*)d_in[3];
    const float* att_src  = (const float*)d_in[4];
    const float* att_dst  = (const float*)d_in[5];
    const float* W_edge   = (const float*)d_in[6];
    const float* att_edge = (const float*)d_in[7];
    const float* gat_bias = (const float*)d_in[8];
    const float* bias     = (const float*)d_in[9];
    float* out = (float*)d_out;

    // one-time resource creation (streams/events are resources, not work)
    static cudaStream_t s_aux = 0;
    static cudaEvent_t  ev_fork = 0, ev_join = 0;
    if (s_aux == 0) {
        cudaStreamCreateWithFlags(&s_aux, cudaStreamNonBlocking);
        cudaEventCreateWithFlags(&ev_fork, cudaEventDisableTiming);
        cudaEventCreateWithFlags(&ev_join, cudaEventDisableTiming);
    }

    // fork: CSR-build chain on aux stream, GEMM path on main stream
    cudaEventRecord(ev_fork, 0);
    cudaStreamWaitEvent(s_aux, ev_fork, 0);

    k_init <<<(N_NODES + 255) / 256, 256, 0, s_aux>>>();
    k_count<<<(N_EDGES / 4 + 255) / 256, 256, 0, s_aux>>>(ei);
    k_scan1<<<N_SCAN_BLKS, 256, 0, s_aux>>>();
    k_scan2<<<1, 32, 0, s_aux>>>();
    k_scan3<<<(N_NODES + 255) / 256, 256, 0, s_aux>>>();
    cudaEventRecord(ev_join, s_aux);

    k_wpw  <<<33, 256>>>(W, W_edge, att_edge);
    k_gemm <<<(N_NODES + 127) / 128, 256>>>(x, att_src, att_dst);

    // join: edge scatter needs gemm (asrc/adst) + cursors + weff
    cudaStreamWaitEvent(0, ev_join, 0);
    k_edge_scatter<<<N_EDGES / 256, 256>>>(ei, ea);
    k_agg         <<<(N_NODES + 7) / 8, 256>>>(out, gat_bias, bias);
}

// round 11
// speedup vs baseline: 1.1008x; 1.1008x over previous
#include <cuda_runtime.h>
#include <cuda_fp16.h>

#define N_NODES 100000
#define N_EDGES 1600000
#define IN_CH 128
#define ED_CH 32
#define HEADS 4
#define CH 32
#define HC 128
#define NEG_SLOPE 0.2f
#define SCAN_BLK 1024
#define N_SCAN_BLKS ((N_NODES + SCAN_BLK - 1) / SCAN_BLK)   // 98

// ---------------- scratch (no runtime allocation allowed) ----------------
__device__ __half g_xh_h[N_NODES * HC];         // 25.6 MB fp16 xh, [N,H,C]
__device__ float g_asrc[N_NODES * HEADS];
__device__ float g_adst[N_NODES * HEADS];
__device__ float g_weff[ED_CH * HEADS];         // folded W_edge @ att_edge
__device__ uint2 g_Wp[16 * 16 * 32];            // W packed as tf32 B-fragments
__device__ uint4 g_rec[N_EDGES];                // {src, ev01(h2), ev23(h2), 0} by dst
__device__ int   g_count[N_NODES];
__device__ int   g_rowptr[N_NODES + 1];
__device__ int   g_cursor[N_NODES];
__device__ int   g_bsum[N_SCAN_BLKS];
__device__ int   g_boff[N_SCAN_BLKS];

__device__ __forceinline__ unsigned tf32r(float f) {
    unsigned r;
    asm("cvt.rna.tf32.f32 %0, %1;" : "=r"(r) : "f"(f));
    return r;
}

__device__ __forceinline__ void mma_tf32(float c[4], unsigned a0, unsigned a1,
                                         unsigned a2, unsigned a3,
                                         unsigned b0, unsigned b1) {
    asm volatile(
        "mma.sync.aligned.m16n8k8.row.col.f32.tf32.tf32.f32 "
        "{%0,%1,%2,%3},{%4,%5,%6,%7},{%8,%9},{%0,%1,%2,%3};"
        : "+f"(c[0]), "+f"(c[1]), "+f"(c[2]), "+f"(c[3])
        : "r"(a0), "r"(a1), "r"(a2), "r"(a3), "r"(b0), "r"(b1));
}

// ---------------- init: zero edge counts ------------------------------------
__global__ void k_init() {
    int i = blockIdx.x * blockDim.x + threadIdx.x;
    if (i < N_NODES) g_count[i] = 0;
}

// ---------------- degree count: 4 edges per thread via int4 -----------------
__global__ __launch_bounds__(256) void k_count(const int* __restrict__ ei) {
    int i = blockIdx.x * 256 + threadIdx.x;        // int4 index
    if (i * 4 < N_EDGES) {
        int4 d4 = *(const int4*)(ei + N_EDGES + i * 4);
        atomicAdd(&g_count[d4.x], 1);
        atomicAdd(&g_count[d4.y], 1);
        atomicAdd(&g_count[d4.z], 1);
        atomicAdd(&g_count[d4.w], 1);
    }
}

// ---------------- W pack (blocks 0..31) | w_eff (block 32) ------------------
__global__ __launch_bounds__(256) void k_wpw(const float* __restrict__ W,
                                             const float* __restrict__ W_edge,
                                             const float* __restrict__ att_edge) {
    int b = blockIdx.x;
    int tid = threadIdx.x;
    if (b < 32) {
        int t = b * 256 + tid;  // 0..8191
        int lane = t & 31;
        int n = (t >> 5) & 15;
        int kk = t >> 9;
        int krow = 8 * kk + (lane & 3);
        int col = 8 * n + (lane >> 2);
        uint2 bb;
        bb.x = tf32r(W[krow * HC + col]);
        bb.y = tf32r(W[(krow + 4) * HC + col]);
        g_Wp[t] = bb;
    } else if (tid < 128) {
        int d = tid >> 2, h = tid & 3;
        float s = 0.f;
        #pragma unroll
        for (int c = 0; c < CH; c++)
            s += W_edge[d * HC + h * CH + c] * att_edge[h * CH + c];
        g_weff[d * HEADS + h] = s;
    }
}

// ---------------- xh = x @ W via tf32 mma + fused a_src/a_dst ---------------
__global__ __launch_bounds__(256) void k_gemm(const float* __restrict__ x,
                                              const float* __restrict__ att_src,
                                              const float* __restrict__ att_dst) {
    int tid  = threadIdx.x;
    int warp = tid >> 5;
    int lane = tid & 31;
    int grp  = lane >> 2;      // 0..7 (row within fragment)
    int q    = lane & 3;       // quad id (col group)

    int r0  = blockIdx.x * 128 + warp * 16;
    int rlo = r0 + grp;
    int rhi = rlo + 8;
    int rloL = rlo < N_NODES ? rlo : N_NODES - 1;
    int rhiL = rhi < N_NODES ? rhi : N_NODES - 1;
    const float* xlo = x + (size_t)rloL * IN_CH;
    const float* xhi = x + (size_t)rhiL * IN_CH;

    float c[16][4];
    #pragma unroll
    for (int n = 0; n < 16; n++) { c[n][0] = c[n][1] = c[n][2] = c[n][3] = 0.f; }

    #pragma unroll
    for (int kk = 0; kk < 16; kk++) {
        int k0 = 8 * kk;
        unsigned a0 = tf32r(__ldg(xlo + k0 + q));
        unsigned a1 = tf32r(__ldg(xhi + k0 + q));
        unsigned a2 = tf32r(__ldg(xlo + k0 + q + 4));
        unsigned a3 = tf32r(__ldg(xhi + k0 + q + 4));
        const uint2* wp = g_Wp + (size_t)kk * 16 * 32 + lane;
        #pragma unroll
        for (int n = 0; n < 16; n++) {
            uint2 b = __ldg(wp + n * 32);
            mma_tf32(c[n], a0, a1, a2, a3, b.x, b.y);
        }
    }

    float sl[4] = {0.f, 0.f, 0.f, 0.f}, dl[4] = {0.f, 0.f, 0.f, 0.f};
    float sh[4] = {0.f, 0.f, 0.f, 0.f}, dh[4] = {0.f, 0.f, 0.f, 0.f};
    bool wlo = rlo < N_NODES, whi = rhi < N_NODES;
    #pragma unroll
    for (int n = 0; n < 16; n++) {
        int col = 8 * n + 2 * q;
        int h = n >> 2;
        float as0 = __ldg(att_src + col), as1 = __ldg(att_src + col + 1);
        float ad0 = __ldg(att_dst + col), ad1 = __ldg(att_dst + col + 1);
        if (wlo)
            *(__half2*)(g_xh_h + (size_t)rlo * HC + col) =
                __floats2half2_rn(c[n][0], c[n][1]);
        if (whi)
            *(__half2*)(g_xh_h + (size_t)rhi * HC + col) =
                __floats2half2_rn(c[n][2], c[n][3]);
        sl[h] += c[n][0] * as0 + c[n][1] * as1;
        dl[h] += c[n][0] * ad0 + c[n][1] * ad1;
        sh[h] += c[n][2] * as0 + c[n][3] * as1;
        dh[h] += c[n][2] * ad0 + c[n][3] * ad1;
    }
    #pragma unroll
    for (int h = 0; h < 4; h++) {
        #pragma unroll
        for (int o = 1; o < 4; o <<= 1) {
            sl[h] += __shfl_xor_sync(0xffffffffu, sl[h], o);
            dl[h] += __shfl_xor_sync(0xffffffffu, dl[h], o);
            sh[h] += __shfl_xor_sync(0xffffffffu, sh[h], o);
            dh[h] += __shfl_xor_sync(0xffffffffu, dh[h], o);
        }
    }
    if (q == 0) {
        #pragma unroll
        for (int h = 0; h < 4; h++) {
            if (wlo) { g_asrc[rlo * HEADS + h] = sl[h]; g_adst[rlo * HEADS + h] = dl[h]; }
            if (whi) { g_asrc[rhi * HEADS + h] = sh[h]; g_adst[rhi * HEADS + h] = dh[h]; }
        }
    }
}

// ---------------- scan step 1: per-1024-block exclusive scan ---------------
__global__ __launch_bounds__(256) void k_scan1() {
    int b = blockIdx.x;
    int base = b * SCAN_BLK;
    int tid = threadIdx.x;
    int lane = tid & 31, w = tid >> 5;
    int v[4], ts = 0;
    #pragma unroll
    for (int j = 0; j < 4; j++) {
        int idx = base + tid * 4 + j;
        v[j] = (idx < N_NODES) ? g_count[idx] : 0;
        ts += v[j];
    }
    int incl = ts;
    #pragma unroll
    for (int o = 1; o < 32; o <<= 1) {
        int t = __shfl_up_sync(0xffffffffu, incl, o);
        if (lane >= o) incl += t;
    }
    __shared__ int wsum[8];
    if (lane == 31) wsum[w] = incl;
    __syncthreads();
    if (w == 0 && lane < 8) {
        int t = wsum[lane];
        #pragma unroll
        for (int o = 1; o < 8; o <<= 1) {
            int u = __shfl_up_sync(0xffu, t, o);
            if (lane >= o) t += u;
        }
        wsum[lane] = t;
    }
    __syncthreads();
    int excl = incl - ts + (w > 0 ? wsum[w - 1] : 0);
    int run = excl;
    #pragma unroll
    for (int j = 0; j < 4; j++) {
        int idx = base + tid * 4 + j;
        if (idx < N_NODES) g_rowptr[idx] = run;
        run += v[j];
    }
    __syncthreads();
    if (tid == 255) g_bsum[b] = wsum[7];
}

// ---------------- scan step 2: warp-parallel scan of 98 block sums ---------
__global__ void k_scan2() {
    int lane = threadIdx.x;            // 32 threads
    int run = 0;
    for (int b0 = 0; b0 < N_SCAN_BLKS; b0 += 32) {
        int i = b0 + lane;
        int v = (i < N_SCAN_BLKS) ? g_bsum[i] : 0;
        int incl = v;
        #pragma unroll
        for (int o = 1; o < 32; o <<= 1) {
            int t = __shfl_up_sync(0xffffffffu, incl, o);
            if (lane >= o) incl += t;
        }
        if (i < N_SCAN_BLKS) g_boff[i] = run + incl - v;
        run += __shfl_sync(0xffffffffu, incl, 31);
    }
    if (lane == 0) g_rowptr[N_NODES] = N_EDGES;
}

// ---------------- scan step 3: add offsets, init cursors -------------------
__global__ void k_scan3() {
    int i = blockIdx.x * blockDim.x + threadIdx.x;
    if (i >= N_NODES) return;
    int r = g_rowptr[i] + g_boff[i >> 10];
    g_rowptr[i] = r;
    g_cursor[i] = r;
}

// ---------------- fused edge pass: logits->exp + CSR scatter ---------------
// thread-per-edge, DIRECT row loads (one 128B line per edge; 8 LDG.128 that
// hit the same line) — no 32KB smem staging, no block-wide barrier for data.
__global__ __launch_bounds__(256) void k_edge_scatter(const int* __restrict__ ei,
                                                      const float* __restrict__ ea) {
    __shared__ float4 sW[32];
    int tid = threadIdx.x;
    int e   = blockIdx.x * 256 + tid;

    if (tid < 32) sW[tid] = *(const float4*)(g_weff + tid * 4);

    // direct row read: 8 x float4 within one 128B line
    float4 r[8];
    const float4* row = (const float4*)(ea + (size_t)e * ED_CH);
    #pragma unroll
    for (int j = 0; j < 8; j++) r[j] = __ldg(row + j);

    __syncthreads();   // sW visibility only

    float s0 = 0.f, s1 = 0.f, s2 = 0.f, s3 = 0.f;
    #pragma unroll
    for (int j = 0; j < 8; j++) {
        const float* rv = (const float*)&r[j];
        #pragma unroll
        for (int c2 = 0; c2 < 4; c2++) {
            float v = rv[c2];
            float4 w = sW[j * 4 + c2];
            s0 += v * w.x; s1 += v * w.y; s2 += v * w.z; s3 += v * w.w;
        }
    }
    int src = __ldg(ei + e);
    int dst = __ldg(ei + N_EDGES + e);
    float4 as = __ldg((const float4*)(g_asrc) + src);
    float4 ad = __ldg((const float4*)(g_adst) + dst);
    float l0 = as.x + ad.x + s0;
    float l1 = as.y + ad.y + s1;
    float l2 = as.z + ad.z + s2;
    float l3 = as.w + ad.w + s3;
    l0 = l0 >= 0.f ? l0 : NEG_SLOPE * l0;
    l1 = l1 >= 0.f ? l1 : NEG_SLOPE * l1;
    l2 = l2 >= 0.f ? l2 : NEG_SLOPE * l2;
    l3 = l3 >= 0.f ? l3 : NEG_SLOPE * l3;
    __half2 p0 = __floats2half2_rn(__expf(l0), __expf(l1));
    __half2 p1 = __floats2half2_rn(__expf(l2), __expf(l3));
    int pos = atomicAdd(&g_cursor[dst], 1);
    uint4 rec;
    rec.x = (unsigned)src;
    rec.y = *(unsigned*)&p0;
    rec.z = *(unsigned*)&p1;
    rec.w = 0u;
    g_rec[pos] = rec;          // single STG.128
}

// ---------------- aggregate: lane-per-(head,4ch), pipelined rec loads ------
__global__ __launch_bounds__(256) void k_agg(float* __restrict__ out,
                                             const float* __restrict__ gat_bias,
                                             const float* __restrict__ bias) {
    int n = blockIdx.x * 8 + (threadIdx.x >> 5);
    if (n >= N_NODES) return;
    int lane = threadIdx.x & 31;
    int h  = lane >> 3;            // head owned by this lane
    int c0 = 4 * (lane & 7);       // channel base (0..28)
    int beg = g_rowptr[n];
    int end = g_rowptr[n + 1];
    float a0 = 0.f, a1 = 0.f, a2 = 0.f, a3 = 0.f, dsum = 0.f;
    uint4 r = (beg < end) ? __ldg(g_rec + beg) : make_uint4(0, 0, 0, 0);
    for (int idx = beg; idx < end; idx++) {
        uint4 rn = (idx + 1 < end) ? __ldg(g_rec + idx + 1) : r;   // prefetch
        int src = (int)r.x;
        unsigned evbits = (h & 2) ? r.z : r.y;
        float2 evp = __half22float2(*(__half2*)&evbits);
        float ev = (h & 1) ? evp.y : evp.x;
        uint2 xw = __ldg((const uint2*)(g_xh_h + (size_t)src * HC) + lane);
        float2 f0 = __half22float2(*(__half2*)&xw.x);
        float2 f1 = __half22float2(*(__half2*)&xw.y);
        a0 += ev * f0.x; a1 += ev * f0.y;
        a2 += ev * f1.x; a3 += ev * f1.y;
        dsum += ev;
        r = rn;
    }
    float inv = dsum > 0.f ? 1.f / dsum : 0.f;
    a0 *= inv; a1 *= inv; a2 *= inv; a3 *= inv;
    #pragma unroll
    for (int o = 8; o < 32; o <<= 1) {
        a0 += __shfl_xor_sync(0xffffffffu, a0, o);
        a1 += __shfl_xor_sync(0xffffffffu, a1, o);
        a2 += __shfl_xor_sync(0xffffffffu, a2, o);
        a3 += __shfl_xor_sync(0xffffffffu, a3, o);
    }
    if (lane < 8) {
        float rr[4] = {a0, a1, a2, a3};
        float4 v4;
        float* vp = (float*)&v4;
        #pragma unroll
        for (int j = 0; j < 4; j++) {
            int c = c0 + j;
            float gb = 0.25f * (__ldg(gat_bias + c)      + __ldg(gat_bias + 32 + c) +
                                __ldg(gat_bias + 64 + c) + __ldg(gat_bias + 96 + c));
            float v = 0.25f * rr[j] + gb + __ldg(bias + c);
            vp[j] = v > 0.f ? v : 0.f;
        }
        *(float4*)(out + (size_t)n * CH + c0) = v4;
    }
}

extern "C" void kernel_launch(void* const* d_in, const int* in_sizes, int n_in,
                              void* d_out, int out_size) {
    const float* x        = (const float*)d_in[0];
    const int*   ei       = (const int*)  d_in[1];
    const float* ea       = (const float*)d_in[2];
    const float* W        = (const float*)d_in[3];
    const float* att_src  = (const float*)d_in[4];
    const float* att_dst  = (const float*)d_in[5];
    const float* W_edge   = (const float*)d_in[6];
    const float* att_edge = (const float*)d_in[7];
    const float* gat_bias = (const float*)d_in[8];
    const float* bias     = (const float*)d_in[9];
    float* out = (float*)d_out;

    // one-time resource creation (streams/events are resources, not work)
    static cudaStream_t s_aux = 0;
    static cudaEvent_t  ev_fork = 0, ev_join = 0;
    if (s_aux == 0) {
        cudaStreamCreateWithFlags(&s_aux, cudaStreamNonBlocking);
        cudaEventCreateWithFlags(&ev_fork, cudaEventDisableTiming);
        cudaEventCreateWithFlags(&ev_join, cudaEventDisableTiming);
    }

    // fork: CSR-build chain on aux stream, GEMM path on main stream
    cudaEventRecord(ev_fork, 0);
    cudaStreamWaitEvent(s_aux, ev_fork, 0);

    k_init <<<(N_NODES + 255) / 256, 256, 0, s_aux>>>();
    k_count<<<(N_EDGES / 4 + 255) / 256, 256, 0, s_aux>>>(ei);
    k_scan1<<<N_SCAN_BLKS, 256, 0, s_aux>>>();
    k_scan2<<<1, 32, 0, s_aux>>>();
    k_scan3<<<(N_NODES + 255) / 256, 256, 0, s_aux>>>();
    cudaEventRecord(ev_join, s_aux);

    k_wpw  <<<33, 256>>>(W, W_edge, att_edge);
    k_gemm <<<(N_NODES + 127) / 128, 256>>>(x, att_src, att_dst);

    // join: edge scatter needs gemm (asrc/adst) + cursors + weff
    cudaStreamWaitEvent(0, ev_join, 0);
    k_edge_scatter<<<N_EDGES / 256, 256>>>(ei, ea);
    k_agg         <<<(N_NODES + 7) / 8, 256>>>(out, gat_bias, bias);
}

// round 12
// speedup vs baseline: 1.1542x; 1.0485x over previous
#include <cuda_runtime.h>
#include <cuda_fp16.h>

#define N_NODES 100000
#define N_EDGES 1600000
#define IN_CH 128
#define ED_CH 32
#define HEADS 4
#define CH 32
#define HC 128
#define NEG_SLOPE 0.2f
#define SCAN_BLK 1024
#define N_SCAN_BLKS ((N_NODES + SCAN_BLK - 1) / SCAN_BLK)   // 98

// ---------------- scratch (no runtime allocation allowed) ----------------
__device__ __half g_xh_h[N_NODES * HC];         // 25.6 MB fp16 xh, [N,H,C]
__device__ float g_asrc[N_NODES * HEADS];
__device__ float g_adst[N_NODES * HEADS];
__device__ float g_weff[ED_CH * HEADS];         // folded W_edge @ att_edge
__device__ uint2 g_Wp[16 * 16 * 32];            // W packed as tf32 B-fragments
__device__ uint4 g_rec[N_EDGES];                // {src, ev01(h2), ev23(h2), 0} by dst
__device__ int   g_pos[N_EDGES];                // intra-node rank (from count pass)
__device__ int   g_count[N_NODES];
__device__ int   g_rowptr[N_NODES + 1];
__device__ int   g_bsum[N_SCAN_BLKS];
__device__ int   g_boff[N_SCAN_BLKS];

__device__ __forceinline__ unsigned tf32r(float f) {
    unsigned r;
    asm("cvt.rna.tf32.f32 %0, %1;" : "=r"(r) : "f"(f));
    return r;
}

__device__ __forceinline__ void mma_tf32(float c[4], unsigned a0, unsigned a1,
                                         unsigned a2, unsigned a3,
                                         unsigned b0, unsigned b1) {
    asm volatile(
        "mma.sync.aligned.m16n8k8.row.col.f32.tf32.tf32.f32 "
        "{%0,%1,%2,%3},{%4,%5,%6,%7},{%8,%9},{%0,%1,%2,%3};"
        : "+f"(c[0]), "+f"(c[1]), "+f"(c[2]), "+f"(c[3])
        : "r"(a0), "r"(a1), "r"(a2), "r"(a3), "r"(b0), "r"(b1));
}

// ---------------- init: zero edge counts ------------------------------------
__global__ void k_init() {
    int i = blockIdx.x * blockDim.x + threadIdx.x;
    if (i < N_NODES) g_count[i] = 0;
}

// ---------------- degree count + intra-node rank (hidden in fork) -----------
__global__ __launch_bounds__(256) void k_count(const int* __restrict__ ei) {
    int i = blockIdx.x * 256 + threadIdx.x;        // int4 index
    if (i * 4 < N_EDGES) {
        int4 d4 = *(const int4*)(ei + N_EDGES + i * 4);
        int4 p4;
        p4.x = atomicAdd(&g_count[d4.x], 1);
        p4.y = atomicAdd(&g_count[d4.y], 1);
        p4.z = atomicAdd(&g_count[d4.z], 1);
        p4.w = atomicAdd(&g_count[d4.w], 1);
        *(int4*)(g_pos + i * 4) = p4;
    }
}

// ---------------- W pack (blocks 0..31) | w_eff (block 32) ------------------
__global__ __launch_bounds__(256) void k_wpw(const float* __restrict__ W,
                                             const float* __restrict__ W_edge,
                                             const float* __restrict__ att_edge) {
    int b = blockIdx.x;
    int tid = threadIdx.x;
    if (b < 32) {
        int t = b * 256 + tid;  // 0..8191
        int lane = t & 31;
        int n = (t >> 5) & 15;
        int kk = t >> 9;
        int krow = 8 * kk + (lane & 3);
        int col = 8 * n + (lane >> 2);
        uint2 bb;
        bb.x = tf32r(W[krow * HC + col]);
        bb.y = tf32r(W[(krow + 4) * HC + col]);
        g_Wp[t] = bb;
    } else if (tid < 128) {
        int d = tid >> 2, h = tid & 3;
        float s = 0.f;
        #pragma unroll
        for (int c = 0; c < CH; c++)
            s += W_edge[d * HC + h * CH + c] * att_edge[h * CH + c];
        g_weff[d * HEADS + h] = s;
    }
}

// ---------------- xh = x @ W via tf32 mma + fused a_src/a_dst ---------------
__global__ __launch_bounds__(256) void k_gemm(const float* __restrict__ x,
                                              const float* __restrict__ att_src,
                                              const float* __restrict__ att_dst) {
    int tid  = threadIdx.x;
    int warp = tid >> 5;
    int lane = tid & 31;
    int grp  = lane >> 2;      // 0..7 (row within fragment)
    int q    = lane & 3;       // quad id (col group)

    int r0  = blockIdx.x * 128 + warp * 16;
    int rlo = r0 + grp;
    int rhi = rlo + 8;
    int rloL = rlo < N_NODES ? rlo : N_NODES - 1;
    int rhiL = rhi < N_NODES ? rhi : N_NODES - 1;
    const float* xlo = x + (size_t)rloL * IN_CH;
    const float* xhi = x + (size_t)rhiL * IN_CH;

    float c[16][4];
    #pragma unroll
    for (int n = 0; n < 16; n++) { c[n][0] = c[n][1] = c[n][2] = c[n][3] = 0.f; }

    #pragma unroll
    for (int kk = 0; kk < 16; kk++) {
        int k0 = 8 * kk;
        unsigned a0 = tf32r(__ldg(xlo + k0 + q));
        unsigned a1 = tf32r(__ldg(xhi + k0 + q));
        unsigned a2 = tf32r(__ldg(xlo + k0 + q + 4));
        unsigned a3 = tf32r(__ldg(xhi + k0 + q + 4));
        const uint2* wp = g_Wp + (size_t)kk * 16 * 32 + lane;
        #pragma unroll
        for (int n = 0; n < 16; n++) {
            uint2 b = __ldg(wp + n * 32);
            mma_tf32(c[n], a0, a1, a2, a3, b.x, b.y);
        }
    }

    float sl[4] = {0.f, 0.f, 0.f, 0.f}, dl[4] = {0.f, 0.f, 0.f, 0.f};
    float sh[4] = {0.f, 0.f, 0.f, 0.f}, dh[4] = {0.f, 0.f, 0.f, 0.f};
    bool wlo = rlo < N_NODES, whi = rhi < N_NODES;
    #pragma unroll
    for (int n = 0; n < 16; n++) {
        int col = 8 * n + 2 * q;
        int h = n >> 2;
        float as0 = __ldg(att_src + col), as1 = __ldg(att_src + col + 1);
        float ad0 = __ldg(att_dst + col), ad1 = __ldg(att_dst + col + 1);
        if (wlo)
            *(__half2*)(g_xh_h + (size_t)rlo * HC + col) =
                __floats2half2_rn(c[n][0], c[n][1]);
        if (whi)
            *(__half2*)(g_xh_h + (size_t)rhi * HC + col) =
                __floats2half2_rn(c[n][2], c[n][3]);
        sl[h] += c[n][0] * as0 + c[n][1] * as1;
        dl[h] += c[n][0] * ad0 + c[n][1] * ad1;
        sh[h] += c[n][2] * as0 + c[n][3] * as1;
        dh[h] += c[n][2] * ad0 + c[n][3] * ad1;
    }
    #pragma unroll
    for (int h = 0; h < 4; h++) {
        #pragma unroll
        for (int o = 1; o < 4; o <<= 1) {
            sl[h] += __shfl_xor_sync(0xffffffffu, sl[h], o);
            dl[h] += __shfl_xor_sync(0xffffffffu, dl[h], o);
            sh[h] += __shfl_xor_sync(0xffffffffu, sh[h], o);
            dh[h] += __shfl_xor_sync(0xffffffffu, dh[h], o);
        }
    }
    if (q == 0) {
        #pragma unroll
        for (int h = 0; h < 4; h++) {
            if (wlo) { g_asrc[rlo * HEADS + h] = sl[h]; g_adst[rlo * HEADS + h] = dl[h]; }
            if (whi) { g_asrc[rhi * HEADS + h] = sh[h]; g_adst[rhi * HEADS + h] = dh[h]; }
        }
    }
}

// ---------------- scan step 1: per-1024-block exclusive scan ---------------
__global__ __launch_bounds__(256) void k_scan1() {
    int b = blockIdx.x;
    int base = b * SCAN_BLK;
    int tid = threadIdx.x;
    int lane = tid & 31, w = tid >> 5;
    int v[4], ts = 0;
    #pragma unroll
    for (int j = 0; j < 4; j++) {
        int idx = base + tid * 4 + j;
        v[j] = (idx < N_NODES) ? g_count[idx] : 0;
        ts += v[j];
    }
    int incl = ts;
    #pragma unroll
    for (int o = 1; o < 32; o <<= 1) {
        int t = __shfl_up_sync(0xffffffffu, incl, o);
        if (lane >= o) incl += t;
    }
    __shared__ int wsum[8];
    if (lane == 31) wsum[w] = incl;
    __syncthreads();
    if (w == 0 && lane < 8) {
        int t = wsum[lane];
        #pragma unroll
        for (int o = 1; o < 8; o <<= 1) {
            int u = __shfl_up_sync(0xffu, t, o);
            if (lane >= o) t += u;
        }
        wsum[lane] = t;
    }
    __syncthreads();
    int excl = incl - ts + (w > 0 ? wsum[w - 1] : 0);
    int run = excl;
    #pragma unroll
    for (int j = 0; j < 4; j++) {
        int idx = base + tid * 4 + j;
        if (idx < N_NODES) g_rowptr[idx] = run;
        run += v[j];
    }
    __syncthreads();
    if (tid == 255) g_bsum[b] = wsum[7];
}

// ---------------- scan step 2: warp-parallel scan of 98 block sums ---------
__global__ void k_scan2() {
    int lane = threadIdx.x;            // 32 threads
    int run = 0;
    for (int b0 = 0; b0 < N_SCAN_BLKS; b0 += 32) {
        int i = b0 + lane;
        int v = (i < N_SCAN_BLKS) ? g_bsum[i] : 0;
        int incl = v;
        #pragma unroll
        for (int o = 1; o < 32; o <<= 1) {
            int t = __shfl_up_sync(0xffffffffu, incl, o);
            if (lane >= o) incl += t;
        }
        if (i < N_SCAN_BLKS) g_boff[i] = run + incl - v;
        run += __shfl_sync(0xffffffffu, incl, 31);
    }
    if (lane == 0) g_rowptr[N_NODES] = N_EDGES;
}

// ---------------- scan step 3: add offsets ---------------------------------
__global__ void k_scan3() {
    int i = blockIdx.x * blockDim.x + threadIdx.x;
    if (i >= N_NODES) return;
    g_rowptr[i] = g_rowptr[i] + g_boff[i >> 10];
}

// ---------------- fused edge pass: logits->exp + CSR scatter ---------------
// R7 staged-smem form; atomic cursor replaced by rowptr[dst] + precomputed rank.
__global__ __launch_bounds__(256) void k_edge_scatter(const int* __restrict__ ei,
                                                      const float* __restrict__ ea) {
    __shared__ float sEA[256][33];
    __shared__ float4 sW[32];
    int tid = threadIdx.x;
    int e0  = blockIdx.x * 256;

    if (tid < 32) sW[tid] = *(const float4*)(g_weff + tid * 4);

    const float4* gsrc = (const float4*)(ea + (size_t)e0 * ED_CH);
    #pragma unroll
    for (int k = 0; k < 8; k++) {
        int idx = tid + k * 256;
        float4 v = gsrc[idx];
        int row = idx >> 3;
        int col = (idx & 7) * 4;
        sEA[row][col + 0] = v.x; sEA[row][col + 1] = v.y;
        sEA[row][col + 2] = v.z; sEA[row][col + 3] = v.w;
    }
    __syncthreads();

    int e = e0 + tid;
    float s0 = 0.f, s1 = 0.f, s2 = 0.f, s3 = 0.f;
    #pragma unroll
    for (int d = 0; d < 32; d++) {
        float v = sEA[tid][d];
        float4 w = sW[d];
        s0 += v * w.x; s1 += v * w.y; s2 += v * w.z; s3 += v * w.w;
    }
    int src = __ldg(ei + e);
    int dst = __ldg(ei + N_EDGES + e);
    float4 as = __ldg((const float4*)(g_asrc) + src);
    float4 ad = __ldg((const float4*)(g_adst) + dst);
    float l0 = as.x + ad.x + s0;
    float l1 = as.y + ad.y + s1;
    float l2 = as.z + ad.z + s2;
    float l3 = as.w + ad.w + s3;
    l0 = l0 >= 0.f ? l0 : NEG_SLOPE * l0;
    l1 = l1 >= 0.f ? l1 : NEG_SLOPE * l1;
    l2 = l2 >= 0.f ? l2 : NEG_SLOPE * l2;
    l3 = l3 >= 0.f ? l3 : NEG_SLOPE * l3;
    __half2 p0 = __floats2half2_rn(__expf(l0), __expf(l1));
    __half2 p1 = __floats2half2_rn(__expf(l2), __expf(l3));
    int pos = __ldg(g_rowptr + dst) + __ldg(g_pos + e);   // no atomic
    uint4 rec;
    rec.x = (unsigned)src;
    rec.y = *(unsigned*)&p0;
    rec.z = *(unsigned*)&p1;
    rec.w = 0u;
    g_rec[pos] = rec;          // single STG.128
}

// ---------------- aggregate: lane-per-(head,4ch), pipelined rec loads ------
__global__ __launch_bounds__(256) void k_agg(float* __restrict__ out,
                                             const float* __restrict__ gat_bias,
                                             const float* __restrict__ bias) {
    int n = blockIdx.x * 8 + (threadIdx.x >> 5);
    if (n >= N_NODES) return;
    int lane = threadIdx.x & 31;
    int h  = lane >> 3;            // head owned by this lane
    int c0 = 4 * (lane & 7);       // channel base (0..28)
    int beg = g_rowptr[n];
    int end = g_rowptr[n + 1];
    float a0 = 0.f, a1 = 0.f, a2 = 0.f, a3 = 0.f, dsum = 0.f;
    uint4 r = (beg < end) ? __ldg(g_rec + beg) : make_uint4(0, 0, 0, 0);
    for (int idx = beg; idx < end; idx++) {
        uint4 rn = (idx + 1 < end) ? __ldg(g_rec + idx + 1) : r;   // prefetch
        int src = (int)r.x;
        unsigned evbits = (h & 2) ? r.z : r.y;
        float2 evp = __half22float2(*(__half2*)&evbits);
        float ev = (h & 1) ? evp.y : evp.x;
        uint2 xw = __ldg((const uint2*)(g_xh_h + (size_t)src * HC) + lane);
        float2 f0 = __half22float2(*(__half2*)&xw.x);
        float2 f1 = __half22float2(*(__half2*)&xw.y);
        a0 += ev * f0.x; a1 += ev * f0.y;
        a2 += ev * f1.x; a3 += ev * f1.y;
        dsum += ev;
        r = rn;
    }
    float inv = dsum > 0.f ? 1.f / dsum : 0.f;
    a0 *= inv; a1 *= inv; a2 *= inv; a3 *= inv;
    #pragma unroll
    for (int o = 8; o < 32; o <<= 1) {
        a0 += __shfl_xor_sync(0xffffffffu, a0, o);
        a1 += __shfl_xor_sync(0xffffffffu, a1, o);
        a2 += __shfl_xor_sync(0xffffffffu, a2, o);
        a3 += __shfl_xor_sync(0xffffffffu, a3, o);
    }
    if (lane < 8) {
        float rr[4] = {a0, a1, a2, a3};
        float4 v4;
        float* vp = (float*)&v4;
        #pragma unroll
        for (int j = 0; j < 4; j++) {
            int c = c0 + j;
            float gb = 0.25f * (__ldg(gat_bias + c)      + __ldg(gat_bias + 32 + c) +
                                __ldg(gat_bias + 64 + c) + __ldg(gat_bias + 96 + c));
            float v = 0.25f * rr[j] + gb + __ldg(bias + c);
            vp[j] = v > 0.f ? v : 0.f;
        }
        *(float4*)(out + (size_t)n * CH + c0) = v4;
    }
}

extern "C" void kernel_launch(void* const* d_in, const int* in_sizes, int n_in,
                              void* d_out, int out_size) {
    const float* x        = (const float*)d_in[0];
    const int*   ei       = (const int*)  d_in[1];
    const float* ea       = (const float*)d_in[2];
    const float* W        = (const float*)d_in[3];
    const float* att_src  = (const float*)d_in[4];
    const float* att_dst  = (const float*)d_in[5];
    const float* W_edge   = (const float*)d_in[6];
    const float* att_edge = (const float*)d_in[7];
    const float* gat_bias = (const float*)d_in[8];
    const float* bias     = (const float*)d_in[9];
    float* out = (float*)d_out;

    // one-time resource creation (streams/events are resources, not work)
    static cudaStream_t s_aux = 0;
    static cudaEvent_t  ev_fork = 0, ev_join = 0;
    if (s_aux == 0) {
        cudaStreamCreateWithFlags(&s_aux, cudaStreamNonBlocking);
        cudaEventCreateWithFlags(&ev_fork, cudaEventDisableTiming);
        cudaEventCreateWithFlags(&ev_join, cudaEventDisableTiming);
    }

    // fork: CSR-build chain on aux stream, GEMM path on main stream
    cudaEventRecord(ev_fork, 0);
    cudaStreamWaitEvent(s_aux, ev_fork, 0);

    k_init <<<(N_NODES + 255) / 256, 256, 0, s_aux>>>();
    k_count<<<(N_EDGES / 4 + 255) / 256, 256, 0, s_aux>>>(ei);
    k_scan1<<<N_SCAN_BLKS, 256, 0, s_aux>>>();
    k_scan2<<<1, 32, 0, s_aux>>>();
    k_scan3<<<(N_NODES + 255) / 256, 256, 0, s_aux>>>();
    cudaEventRecord(ev_join, s_aux);

    k_wpw  <<<33, 256>>>(W, W_edge, att_edge);
    k_gemm <<<(N_NODES + 127) / 128, 256>>>(x, att_src, att_dst);

    // join: edge scatter needs gemm (asrc/adst) + rowptr/pos + weff
    cudaStreamWaitEvent(0, ev_join, 0);
    k_edge_scatter<<<N_EDGES / 256, 256>>>(ei, ea);
    k_agg         <<<(N_NODES + 7) / 8, 256>>>(out, gat_bias, bias);
}